// round 2
// baseline (speedup 1.0000x reference)
#include <cuda_runtime.h>
#include <math.h>

// L=8,B=8,N=4,HIN=1024,D=1024,NH=16,KVH=8,HD=64,FF=3072,W=1024,DOUT=1024, M=B*N=32

__device__ float g_scratch[360448];
#define OFF_H    0
#define OFF_X    32768
#define OFF_QKV  65536
#define OFF_ATT  131072
#define OFF_GU   163840

__device__ __forceinline__ void ffma2(unsigned long long &a,
                                      unsigned long long x,
                                      unsigned long long w) {
    asm("fma.rn.f32x2 %0, %1, %2, %0;" : "+l"(a) : "l"(x), "l"(w));
}

// ---- KV cache shift: dst rows 0..1019 = src rows 4..1023 (per 512 K slabs + 512 V slabs)
__global__ void kvcopy_kernel(const float* __restrict__ pk, const float* __restrict__ pv,
                              float* __restrict__ ks, float* __restrict__ vs) {
    int slab = blockIdx.y, s = slab & 511;
    const float* src = (slab < 512) ? pk : pv;
    float*       dst = (slab < 512) ? ks : vs;
    const float4* s4 = (const float4*)(src + (size_t)s * 65536 + 256);
    float4*       d4 = (float4*)(dst + (size_t)s * 65536);
    for (int i = blockIdx.x * 256 + threadIdx.x; i < 16320; i += gridDim.x * 256)
        d4[i] = s4[i];
}

__global__ void zero_kernel(float* p) {
    ((float4*)p)[blockIdx.x * 256 + threadIdx.x] = make_float4(0.f, 0.f, 0.f, 0.f);
}

// ---- RMSNorm over 1024 cols (+ zero an accumulator buffer)
__global__ void rms_kernel(const float* __restrict__ hin, const float* __restrict__ w,
                           float* __restrict__ xout, float* __restrict__ zbuf, int zn4) {
    __shared__ float sw[8];
    int m = blockIdx.x, tid = threadIdx.x;
    float4 v = ((const float4*)(hin + m * 1024))[tid];
    float ss = v.x * v.x + v.y * v.y + v.z * v.z + v.w * v.w;
    for (int o = 16; o; o >>= 1) ss += __shfl_xor_sync(~0u, ss, o);
    if ((tid & 31) == 0) sw[tid >> 5] = ss;
    __syncthreads();
    if (tid < 32) {
        float z = (tid < 8) ? sw[tid] : 0.f;
        for (int o = 4; o; o >>= 1) z += __shfl_xor_sync(~0u, z, o);
        if (tid == 0) sw[0] = z;
    }
    __syncthreads();
    float rs = rsqrtf(sw[0] * (1.0f / 1024.0f) + 1e-6f);
    float4 wv = ((const float4*)w)[tid];
    ((float4*)(xout + m * 1024))[tid] =
        make_float4(v.x * rs * wv.x, v.y * rs * wv.y, v.z * rs * wv.z, v.w * rs * wv.w);
    if (zbuf) {
        float4 zz = make_float4(0.f, 0.f, 0.f, 0.f);
        for (int i = m * 256 + tid; i < zn4; i += 8192) ((float4*)zbuf)[i] = zz;
    }
}

// ---- skinny GEMM: out[32,*] (+)= x[32,K] @ W[K,*]; 256 cols/block, split-K atomics.
// Up to 3 column segments (boundaries b1,b2). uoff!=0 -> x = silu(g)*u (SwiGLU).
// omode=1 -> transposed epilogue for new_hidden [B,DOUT,N].
__global__ __launch_bounds__(128) void gemm32_kernel(
    const float* __restrict__ xin, int xstride, int uoff,
    const float* __restrict__ w0, const float* __restrict__ w1, const float* __restrict__ w2,
    int ld0, int ld1, int ld2, int b1, int b2,
    float* __restrict__ out, int ostride, int omode, int kchunk) {
    __shared__ __align__(16) float2 xs[32][32];
    int tid = threadIdx.x, col0 = blockIdx.x * 256, kbase = blockIdx.y * kchunk;
    const float* w; int ld, c0;
    if (col0 < b1)      { w = w0; ld = ld0; c0 = col0; }
    else if (col0 < b2) { w = w1; ld = ld1; c0 = col0 - b1; }
    else                { w = w2; ld = ld2; c0 = col0 - b2; }
    int mycol = c0 + 2 * tid;

    unsigned long long acc[32];
#pragma unroll
    for (int m = 0; m < 32; m++) acc[m] = 0ull;

    for (int kc = 0; kc < kchunk; kc += 32) {
        int kb = kbase + kc;
        __syncthreads();
        {
            int k = tid & 31, mr = tid >> 5;
#pragma unroll
            for (int mm = mr; mm < 32; mm += 4) {
                float v = xin[mm * xstride + kb + k];
                if (uoff) {
                    float uu = xin[mm * xstride + uoff + kb + k];
                    v = (v / (1.0f + expf(-v))) * uu;
                }
                xs[mm][k] = make_float2(v, v);
            }
        }
        __syncthreads();
        const float* wp = w + (size_t)kb * ld + mycol;
#pragma unroll 4
        for (int kp = 0; kp < 16; kp++) {
            unsigned long long wA = *(const unsigned long long*)(wp);
            unsigned long long wB = *(const unsigned long long*)(wp + ld);
            wp += 2 * ld;
#pragma unroll
            for (int m = 0; m < 32; m++) {
                ulonglong2 xv = *(const ulonglong2*)(&xs[m][2 * kp]);
                ffma2(acc[m], xv.x, wA);
                ffma2(acc[m], xv.y, wB);
            }
        }
    }
#pragma unroll
    for (int m = 0; m < 32; m++) {
        float lo = __uint_as_float((unsigned)acc[m]);
        float hi = __uint_as_float((unsigned)(acc[m] >> 32));
        if (omode == 0) {
            atomicAdd(out + m * ostride + col0 + 2 * tid, lo);
            atomicAdd(out + m * ostride + col0 + 2 * tid + 1, hi);
        } else {
            int bb = m >> 2, t = m & 3;
            atomicAdd(out + (bb * 1024 + col0 + 2 * tid) * 4 + t, lo);
            atomicAdd(out + (bb * 1024 + col0 + 2 * tid + 1) * 4 + t, hi);
        }
    }
}

// ---- per-head RMS + RoPE; q in-place, new k/v -> cache rows 1020+t
__global__ __launch_bounds__(128) void rope_kernel(
    float* __restrict__ qkv, const float* __restrict__ qn, const float* __restrict__ kn,
    float* __restrict__ ks, float* __restrict__ vs, int l) {
    int gw = blockIdx.x * 4 + (threadIdx.x >> 5), lane = threadIdx.x & 31;
    int m = gw / 24, slot = gw - m * 24, t = m & 3, b = m >> 2;

    float invf = 1.0f / powf(1.0e6f, (float)lane * (1.0f / 32.0f));  // fp32, as JAX
    float angf = (float)(1024 + t) * invf;                            // fp32 angle, as JAX
    double ad = (double)angf;
    float c = (float)cos(ad), s = (float)sin(ad);

    float* base; const float* wn;
    if (slot < 16) { base = qkv + m * 2048 + slot * 64;               wn = qn; }
    else           { base = qkv + m * 2048 + 1024 + (slot - 16) * 64; wn = kn; }

    float a = base[lane], bb = base[lane + 32];
    float ss = a * a + bb * bb;
    for (int o = 16; o; o >>= 1) ss += __shfl_xor_sync(~0u, ss, o);
    float rs = rsqrtf(ss * (1.0f / 64.0f) + 1e-6f);
    float ya = a * rs * wn[lane], yb = bb * rs * wn[lane + 32];
    float oa = ya * c - yb * s, ob = yb * c + ya * s;

    if (slot < 16) { base[lane] = oa; base[lane + 32] = ob; }
    else {
        int kvh = slot - 16;
        size_t off = ((size_t)((l * 8 + b) * 8 + kvh)) * 65536 + (size_t)(1020 + t) * 64;
        ks[off + lane] = oa; ks[off + lane + 32] = ob;
        const float* vb = qkv + m * 2048 + 1536 + kvh * 64;
        vs[off + lane] = vb[lane]; vs[off + lane + 32] = vb[lane + 32];
    }
}

// ---- attention: block per (b,h); 4 queries x 1024 keys, HD=64
__global__ __launch_bounds__(256) void attn_kernel(
    const float* __restrict__ qbuf, const float* __restrict__ ks,
    const float* __restrict__ vs, float* __restrict__ att, int l) {
    __shared__ __align__(16) float qs[4][64];
    __shared__ float ps[4][1024];
    __shared__ float red[2048];
    __shared__ float smax[4], ssum[4], swarp[8];
    int tid = threadIdx.x, b = blockIdx.x >> 4, h = blockIdx.x & 15, kvh = h >> 1;

    { int t = tid >> 6, d = tid & 63;
      qs[t][d] = qbuf[(b * 4 + t) * 2048 + h * 64 + d]; }
    __syncthreads();

    const float* kc = ks + ((size_t)((l * 8 + b) * 8 + kvh)) * 65536;
    const float* vc = vs + ((size_t)((l * 8 + b) * 8 + kvh)) * 65536;

    for (int r = 0; r < 4; r++) {
        int j = tid + (r << 8);
        const float4* kp = (const float4*)(kc + (size_t)j * 64);
        float a0 = 0.f, a1 = 0.f, a2 = 0.f, a3 = 0.f;
#pragma unroll
        for (int d4 = 0; d4 < 16; d4++) {
            float4 kv = kp[d4];
            float4 q0 = *(const float4*)&qs[0][d4 * 4];
            float4 q1 = *(const float4*)&qs[1][d4 * 4];
            float4 q2 = *(const float4*)&qs[2][d4 * 4];
            float4 q3 = *(const float4*)&qs[3][d4 * 4];
            a0 += kv.x * q0.x + kv.y * q0.y + kv.z * q0.z + kv.w * q0.w;
            a1 += kv.x * q1.x + kv.y * q1.y + kv.z * q1.z + kv.w * q1.w;
            a2 += kv.x * q2.x + kv.y * q2.y + kv.z * q2.z + kv.w * q2.w;
            a3 += kv.x * q3.x + kv.y * q3.y + kv.z * q3.z + kv.w * q3.w;
        }
        ps[0][j] = a0 * 0.125f + ((j <= 1020) ? 0.f : -10000.f);
        ps[1][j] = a1 * 0.125f + ((j <= 1021) ? 0.f : -10000.f);
        ps[2][j] = a2 * 0.125f + ((j <= 1022) ? 0.f : -10000.f);
        ps[3][j] = a3 * 0.125f;
    }
    __syncthreads();

    int lane = tid & 31, wid = tid >> 5;
    for (int t = 0; t < 4; t++) {
        float v = -1e30f;
        for (int j = tid; j < 1024; j += 256) v = fmaxf(v, ps[t][j]);
        for (int o = 16; o; o >>= 1) v = fmaxf(v, __shfl_xor_sync(~0u, v, o));
        if (lane == 0) swarp[wid] = v;
        __syncthreads();
        if (tid == 0) { float z = swarp[0]; for (int i = 1; i < 8; i++) z = fmaxf(z, swarp[i]); smax[t] = z; }
        __syncthreads();
    }
    float psum[4] = {0.f, 0.f, 0.f, 0.f};
    for (int t = 0; t < 4; t++)
        for (int j = tid; j < 1024; j += 256) {
            float e = expf(ps[t][j] - smax[t]);
            ps[t][j] = e; psum[t] += e;
        }
    for (int t = 0; t < 4; t++) {
        float v = psum[t];
        for (int o = 16; o; o >>= 1) v += __shfl_xor_sync(~0u, v, o);
        if (lane == 0) swarp[wid] = v;
        __syncthreads();
        if (tid == 0) { float z = 0.f; for (int i = 0; i < 8; i++) z += swarp[i]; ssum[t] = z; }
        __syncthreads();
    }
    {
        int u = tid & 31, s = tid >> 5;
        float oo[4][2] = {{0,0},{0,0},{0,0},{0,0}};
        const float2* v2p = (const float2*)vc;
        for (int j = s * 128; j < s * 128 + 128; j++) {
            float2 v2 = v2p[j * 32 + u];
#pragma unroll
            for (int t = 0; t < 4; t++) { oo[t][0] += ps[t][j] * v2.x; oo[t][1] += ps[t][j] * v2.y; }
        }
#pragma unroll
        for (int t = 0; t < 4; t++) {
            red[((s * 4 + t) * 32 + u) * 2 + 0] = oo[t][0];
            red[((s * 4 + t) * 32 + u) * 2 + 1] = oo[t][1];
        }
    }
    __syncthreads();
    {
        int t = tid >> 6, d = tid & 63, u = d >> 1, c = d & 1;
        float z = 0.f;
#pragma unroll
        for (int si = 0; si < 8; si++) z += red[((si * 4 + t) * 32 + u) * 2 + c];
        att[(b * 4 + t) * 1024 + h * 64 + d] = z / ssum[t];
    }
}

extern "C" void kernel_launch(void* const* d_in, const int* in_sizes, int n_in,
                              void* d_out, int out_size) {
    const float* hidden = (const float*)d_in[0];
    const float* pk     = (const float*)d_in[1];
    const float* pv     = (const float*)d_in[2];
    const float* Win    = (const float*)d_in[3];
    const float* Wout   = (const float*)d_in[4];
    const float* normw  = (const float*)d_in[5];
    const float* Wq     = (const float*)d_in[6];
    const float* Wk     = (const float*)d_in[7];
    const float* Wv     = (const float*)d_in[8];
    const float* Wo     = (const float*)d_in[9];
    const float* ln1    = (const float*)d_in[10];
    const float* ln2    = (const float*)d_in[11];
    const float* qn     = (const float*)d_in[12];
    const float* kn     = (const float*)d_in[13];
    const float* Wg     = (const float*)d_in[14];
    const float* Wu     = (const float*)d_in[15];
    const float* Wd     = (const float*)d_in[16];

    float* outp = (float*)d_out;
    float* oh  = outp;
    float* oks = outp + 32768;
    float* ovs = outp + 32768 + 33554432;

    float* sc = 0;
    cudaGetSymbolAddress((void**)&sc, g_scratch);
    float* h   = sc + OFF_H;
    float* x   = sc + OFF_X;
    float* qkv = sc + OFF_QKV;
    float* att = sc + OFF_ATT;
    float* gu  = sc + OFF_GU;
    const int BIG = 1 << 30;

    kvcopy_kernel<<<dim3(16, 1024), 256>>>(pk, pv, oks, ovs);
    zero_kernel<<<32, 256>>>(h);
    gemm32_kernel<<<dim3(4, 32), 128>>>(hidden, 1024, 0, Win, Win, Win,
        1024, 1024, 1024, BIG, BIG, h, 1024, 0, 32);

    for (int l = 0; l < 8; l++) {
        rms_kernel<<<32, 256>>>(h, ln1 + l * 1024, x, qkv, 16384);
        gemm32_kernel<<<dim3(8, 16), 128>>>(x, 1024, 0,
            Wq + (size_t)l * 1048576, Wk + (size_t)l * 524288, Wv + (size_t)l * 524288,
            1024, 512, 512, 1024, 1536, qkv, 2048, 0, 64);
        rope_kernel<<<192, 128>>>(qkv, qn + l * 64, kn + l * 64, oks, ovs, l);
        attn_kernel<<<128, 256>>>(qkv, oks, ovs, att, l);
        gemm32_kernel<<<dim3(4, 32), 128>>>(att, 1024, 0,
            Wo + (size_t)l * 1048576, Wo, Wo, 1024, 1024, 1024, BIG, BIG, h, 1024, 0, 32);
        rms_kernel<<<32, 256>>>(h, ln2 + l * 1024, x, gu, 49152);
        gemm32_kernel<<<dim3(24, 8), 128>>>(x, 1024, 0,
            Wg + (size_t)l * 3145728, Wu + (size_t)l * 3145728, Wu,
            3072, 3072, 3072, 3072, BIG, gu, 6144, 0, 128);
        gemm32_kernel<<<dim3(4, 24), 128>>>(gu, 6144, 3072,
            Wd + (size_t)l * 3145728, Wd, Wd, 1024, 1024, 1024, BIG, BIG, h, 1024, 0, 128);
    }

    rms_kernel<<<32, 256>>>(h, normw, x, oh, 8192);
    gemm32_kernel<<<dim3(4, 32), 128>>>(x, 1024, 0, Wout, Wout, Wout,
        1024, 1024, 1024, BIG, BIG, oh, 1024, 1, 32);
}

// round 3
// speedup vs baseline: 1.3736x; 1.3736x over previous
#include <cuda_runtime.h>
#include <math.h>

// L=8,B=8,N=4,HIN=1024,D=1024,NH=16,KVH=8,HD=64,FF=3072,W=1024,DOUT=1024, M=B*N=32

__device__ float g_scratch[360448];
#define OFF_H    0
#define OFF_X    32768
#define OFF_QKV  65536
#define OFF_ATT  131072
#define OFF_GU   163840

__device__ __forceinline__ void ffma2(unsigned long long &a,
                                      unsigned long long x,
                                      unsigned long long w) {
    asm("fma.rn.f32x2 %0, %1, %2, %0;" : "+l"(a) : "l"(x), "l"(w));
}

// ---- KV cache shift
__global__ void kvcopy_kernel(const float* __restrict__ pk, const float* __restrict__ pv,
                              float* __restrict__ ks, float* __restrict__ vs) {
    int slab = blockIdx.y, s = slab & 511;
    const float* src = (slab < 512) ? pk : pv;
    float*       dst = (slab < 512) ? ks : vs;
    const float4* s4 = (const float4*)(src + (size_t)s * 65536 + 256);
    float4*       d4 = (float4*)(dst + (size_t)s * 65536);
    for (int i = blockIdx.x * 256 + threadIdx.x; i < 16320; i += gridDim.x * 256)
        d4[i] = s4[i];
}

__global__ void zero_kernel(float* p) {
    ((float4*)p)[blockIdx.x * 256 + threadIdx.x] = make_float4(0.f, 0.f, 0.f, 0.f);
}

// ---- RMSNorm over 1024 cols (+ zero an accumulator buffer)
__global__ void rms_kernel(const float* __restrict__ hin, const float* __restrict__ w,
                           float* __restrict__ xout, float* __restrict__ zbuf, int zn4) {
    __shared__ float sw[8];
    int m = blockIdx.x, tid = threadIdx.x;
    float4 v = ((const float4*)(hin + m * 1024))[tid];
    float ss = v.x * v.x + v.y * v.y + v.z * v.z + v.w * v.w;
    for (int o = 16; o; o >>= 1) ss += __shfl_xor_sync(~0u, ss, o);
    if ((tid & 31) == 0) sw[tid >> 5] = ss;
    __syncthreads();
    if (tid < 32) {
        float z = (tid < 8) ? sw[tid] : 0.f;
        for (int o = 4; o; o >>= 1) z += __shfl_xor_sync(~0u, z, o);
        if (tid == 0) sw[0] = z;
    }
    __syncthreads();
    float rs = rsqrtf(sw[0] * (1.0f / 1024.0f) + 1e-6f);
    float4 wv = ((const float4*)w)[tid];
    ((float4*)(xout + m * 1024))[tid] =
        make_float4(v.x * rs * wv.x, v.y * rs * wv.y, v.z * rs * wv.z, v.w * rs * wv.w);
    if (zbuf) {
        float4 zz = make_float4(0.f, 0.f, 0.f, 0.f);
        for (int i = m * 256 + tid; i < zn4; i += 8192) ((float4*)zbuf)[i] = zz;
    }
}

// ---- skinny GEMM: out[32,*] (+)= x[32,K] @ W[K,*]
// 256 threads: warp-half 0 -> m 0..15, warp-half 1 -> m 16..31.
// CP = cols per thread (2 or 4); block covers 128*CP cols. Split-K via grid.y,
// fp32 atomicAdd epilogue. Up to 3 column segments (boundaries b1,b2).
// uoff!=0 -> x = silu(g)*u (SwiGLU). omode=1 -> transposed epilogue [B,DOUT,N].
template<int CP>
__global__ __launch_bounds__(256) void gemm32(
    const float* __restrict__ xin, int xstride, int uoff,
    const float* __restrict__ w0, const float* __restrict__ w1, const float* __restrict__ w2,
    int ld0, int ld1, int ld2, int b1, int b2,
    float* __restrict__ out, int ostride, int omode, int kchunk) {
    constexpr int CB = 128 * CP;
    constexpr int NC = CP / 2;
    __shared__ __align__(16) float2 xs[32][32];
    int tid = threadIdx.x;
    int t = tid & 127;
    int mbase = (tid >> 7) << 4;           // 0 or 16
    int col0 = blockIdx.x * CB, kbase = blockIdx.y * kchunk;
    const float* w; int ld, c0;
    if (col0 < b1)      { w = w0; ld = ld0; c0 = col0; }
    else if (col0 < b2) { w = w1; ld = ld1; c0 = col0 - b1; }
    else                { w = w2; ld = ld2; c0 = col0 - b2; }
    int mycol = c0 + CP * t;

    unsigned long long acc[16][NC];
#pragma unroll
    for (int m = 0; m < 16; m++)
#pragma unroll
        for (int c = 0; c < NC; c++) acc[m][c] = 0ull;

    for (int kc = 0; kc < kchunk; kc += 32) {
        int kb = kbase + kc;
        __syncthreads();
        {
            int k = tid & 31, mr = tid >> 5;
#pragma unroll
            for (int mm = mr; mm < 32; mm += 8) {
                float v = xin[mm * xstride + kb + k];
                if (uoff) {
                    float uu = xin[mm * xstride + uoff + kb + k];
                    v = (v / (1.0f + expf(-v))) * uu;
                }
                xs[mm][k] = make_float2(v, v);
            }
        }
        __syncthreads();
        const float* wp = w + (size_t)kb * ld + mycol;
#pragma unroll 4
        for (int kp = 0; kp < 16; kp++) {
            unsigned long long wA[NC], wB[NC];
            if (CP == 2) {
                wA[0] = *(const unsigned long long*)(wp);
                wB[0] = *(const unsigned long long*)(wp + ld);
            } else {
                ulonglong2 a2 = *(const ulonglong2*)(wp);
                ulonglong2 b2v = *(const ulonglong2*)(wp + ld);
                wA[0] = a2.x; wA[NC - 1] = a2.y;
                wB[0] = b2v.x; wB[NC - 1] = b2v.y;
            }
            wp += 2 * ld;
#pragma unroll
            for (int m = 0; m < 16; m++) {
                ulonglong2 xv = *(const ulonglong2*)(&xs[mbase + m][2 * kp]);
#pragma unroll
                for (int c = 0; c < NC; c++) {
                    ffma2(acc[m][c], xv.x, wA[c]);
                    ffma2(acc[m][c], xv.y, wB[c]);
                }
            }
        }
    }
#pragma unroll
    for (int m = 0; m < 16; m++) {
#pragma unroll
        for (int c = 0; c < NC; c++) {
            float lo = __uint_as_float((unsigned)acc[m][c]);
            float hi = __uint_as_float((unsigned)(acc[m][c] >> 32));
            int mg = mbase + m;
            int cg = col0 + CP * t + 2 * c;
            if (omode == 0) {
                atomicAdd(out + mg * ostride + cg, lo);
                atomicAdd(out + mg * ostride + cg + 1, hi);
            } else {
                int bb = mg >> 2, tt = mg & 3;
                atomicAdd(out + (bb * 1024 + cg) * 4 + tt, lo);
                atomicAdd(out + (bb * 1024 + cg + 1) * 4 + tt, hi);
            }
        }
    }
}

// ---- per-head RMS + RoPE; q in-place, new k/v -> cache rows 1020+t
__global__ __launch_bounds__(128) void rope_kernel(
    float* __restrict__ qkv, const float* __restrict__ qn, const float* __restrict__ kn,
    float* __restrict__ ks, float* __restrict__ vs, int l) {
    int gw = blockIdx.x * 4 + (threadIdx.x >> 5), lane = threadIdx.x & 31;
    int m = gw / 24, slot = gw - m * 24, t = m & 3, b = m >> 2;

    float invf = 1.0f / powf(1.0e6f, (float)lane * (1.0f / 32.0f));
    float angf = (float)(1024 + t) * invf;
    double ad = (double)angf;
    float c = (float)cos(ad), s = (float)sin(ad);

    float* base; const float* wn;
    if (slot < 16) { base = qkv + m * 2048 + slot * 64;               wn = qn; }
    else           { base = qkv + m * 2048 + 1024 + (slot - 16) * 64; wn = kn; }

    float a = base[lane], bb = base[lane + 32];
    float ss = a * a + bb * bb;
    for (int o = 16; o; o >>= 1) ss += __shfl_xor_sync(~0u, ss, o);
    float rs = rsqrtf(ss * (1.0f / 64.0f) + 1e-6f);
    float ya = a * rs * wn[lane], yb = bb * rs * wn[lane + 32];
    float oa = ya * c - yb * s, ob = yb * c + ya * s;

    if (slot < 16) { base[lane] = oa; base[lane + 32] = ob; }
    else {
        int kvh = slot - 16;
        size_t off = ((size_t)((l * 8 + b) * 8 + kvh)) * 65536 + (size_t)(1020 + t) * 64;
        ks[off + lane] = oa; ks[off + lane + 32] = ob;
        const float* vb = qkv + m * 2048 + 1536 + kvh * 64;
        vs[off + lane] = vb[lane]; vs[off + lane + 32] = vb[lane + 32];
    }
}

// ---- attention: block per (b,h); 4 queries x 1024 keys, HD=64
__global__ __launch_bounds__(256) void attn_kernel(
    const float* __restrict__ qbuf, const float* __restrict__ ks,
    const float* __restrict__ vs, float* __restrict__ att, int l) {
    __shared__ __align__(16) float qs[4][64];
    __shared__ float ps[4][1024];
    __shared__ float red[2048];
    __shared__ float smax[4], ssum[4], swarp[8];
    int tid = threadIdx.x, b = blockIdx.x >> 4, h = blockIdx.x & 15, kvh = h >> 1;

    { int t = tid >> 6, d = tid & 63;
      qs[t][d] = qbuf[(b * 4 + t) * 2048 + h * 64 + d]; }
    __syncthreads();

    const float* kc = ks + ((size_t)((l * 8 + b) * 8 + kvh)) * 65536;
    const float* vc = vs + ((size_t)((l * 8 + b) * 8 + kvh)) * 65536;

    for (int r = 0; r < 4; r++) {
        int j = tid + (r << 8);
        const float4* kp = (const float4*)(kc + (size_t)j * 64);
        float a0 = 0.f, a1 = 0.f, a2 = 0.f, a3 = 0.f;
#pragma unroll
        for (int d4 = 0; d4 < 16; d4++) {
            float4 kv = kp[d4];
            float4 q0 = *(const float4*)&qs[0][d4 * 4];
            float4 q1 = *(const float4*)&qs[1][d4 * 4];
            float4 q2 = *(const float4*)&qs[2][d4 * 4];
            float4 q3 = *(const float4*)&qs[3][d4 * 4];
            a0 += kv.x * q0.x + kv.y * q0.y + kv.z * q0.z + kv.w * q0.w;
            a1 += kv.x * q1.x + kv.y * q1.y + kv.z * q1.z + kv.w * q1.w;
            a2 += kv.x * q2.x + kv.y * q2.y + kv.z * q2.z + kv.w * q2.w;
            a3 += kv.x * q3.x + kv.y * q3.y + kv.z * q3.z + kv.w * q3.w;
        }
        ps[0][j] = a0 * 0.125f + ((j <= 1020) ? 0.f : -10000.f);
        ps[1][j] = a1 * 0.125f + ((j <= 1021) ? 0.f : -10000.f);
        ps[2][j] = a2 * 0.125f + ((j <= 1022) ? 0.f : -10000.f);
        ps[3][j] = a3 * 0.125f;
    }
    __syncthreads();

    int lane = tid & 31, wid = tid >> 5;
    for (int t = 0; t < 4; t++) {
        float v = -1e30f;
        for (int j = tid; j < 1024; j += 256) v = fmaxf(v, ps[t][j]);
        for (int o = 16; o; o >>= 1) v = fmaxf(v, __shfl_xor_sync(~0u, v, o));
        if (lane == 0) swarp[wid] = v;
        __syncthreads();
        if (tid == 0) { float z = swarp[0]; for (int i = 1; i < 8; i++) z = fmaxf(z, swarp[i]); smax[t] = z; }
        __syncthreads();
    }
    float psum[4] = {0.f, 0.f, 0.f, 0.f};
    for (int t = 0; t < 4; t++)
        for (int j = tid; j < 1024; j += 256) {
            float e = expf(ps[t][j] - smax[t]);
            ps[t][j] = e; psum[t] += e;
        }
    for (int t = 0; t < 4; t++) {
        float v = psum[t];
        for (int o = 16; o; o >>= 1) v += __shfl_xor_sync(~0u, v, o);
        if (lane == 0) swarp[wid] = v;
        __syncthreads();
        if (tid == 0) { float z = 0.f; for (int i = 0; i < 8; i++) z += swarp[i]; ssum[t] = z; }
        __syncthreads();
    }
    {
        int u = tid & 31, s = tid >> 5;
        float oo[4][2] = {{0,0},{0,0},{0,0},{0,0}};
        const float2* v2p = (const float2*)vc;
        for (int j = s * 128; j < s * 128 + 128; j++) {
            float2 v2 = v2p[j * 32 + u];
#pragma unroll
            for (int t = 0; t < 4; t++) { oo[t][0] += ps[t][j] * v2.x; oo[t][1] += ps[t][j] * v2.y; }
        }
#pragma unroll
        for (int t = 0; t < 4; t++) {
            red[((s * 4 + t) * 32 + u) * 2 + 0] = oo[t][0];
            red[((s * 4 + t) * 32 + u) * 2 + 1] = oo[t][1];
        }
    }
    __syncthreads();
    {
        int t = tid >> 6, d = tid & 63, u = d >> 1, c = d & 1;
        float z = 0.f;
#pragma unroll
        for (int si = 0; si < 8; si++) z += red[((si * 4 + t) * 32 + u) * 2 + c];
        att[(b * 4 + t) * 1024 + h * 64 + d] = z / ssum[t];
    }
}

extern "C" void kernel_launch(void* const* d_in, const int* in_sizes, int n_in,
                              void* d_out, int out_size) {
    const float* hidden = (const float*)d_in[0];
    const float* pk     = (const float*)d_in[1];
    const float* pv     = (const float*)d_in[2];
    const float* Win    = (const float*)d_in[3];
    const float* Wout   = (const float*)d_in[4];
    const float* normw  = (const float*)d_in[5];
    const float* Wq     = (const float*)d_in[6];
    const float* Wk     = (const float*)d_in[7];
    const float* Wv     = (const float*)d_in[8];
    const float* Wo     = (const float*)d_in[9];
    const float* ln1    = (const float*)d_in[10];
    const float* ln2    = (const float*)d_in[11];
    const float* qn     = (const float*)d_in[12];
    const float* kn     = (const float*)d_in[13];
    const float* Wg     = (const float*)d_in[14];
    const float* Wu     = (const float*)d_in[15];
    const float* Wd     = (const float*)d_in[16];

    float* outp = (float*)d_out;
    float* oh  = outp;
    float* oks = outp + 32768;
    float* ovs = outp + 32768 + 33554432;

    float* sc = 0;
    cudaGetSymbolAddress((void**)&sc, g_scratch);
    float* h   = sc + OFF_H;
    float* x   = sc + OFF_X;
    float* qkv = sc + OFF_QKV;
    float* att = sc + OFF_ATT;
    float* gu  = sc + OFF_GU;
    const int BIG = 1 << 30;

    kvcopy_kernel<<<dim3(16, 1024), 256>>>(pk, pv, oks, ovs);
    zero_kernel<<<32, 256>>>(h);
    gemm32<2><<<dim3(4, 32), 256>>>(hidden, 1024, 0, Win, Win, Win,
        1024, 1024, 1024, BIG, BIG, h, 1024, 0, 32);

    for (int l = 0; l < 8; l++) {
        rms_kernel<<<32, 256>>>(h, ln1 + l * 1024, x, qkv, 16384);
        gemm32<4><<<dim3(4, 32), 256>>>(x, 1024, 0,
            Wq + (size_t)l * 1048576, Wk + (size_t)l * 524288, Wv + (size_t)l * 524288,
            1024, 512, 512, 1024, 1536, qkv, 2048, 0, 32);
        rope_kernel<<<192, 128>>>(qkv, qn + l * 64, kn + l * 64, oks, ovs, l);
        attn_kernel<<<128, 256>>>(qkv, oks, ovs, att, l);
        gemm32<2><<<dim3(4, 32), 256>>>(att, 1024, 0,
            Wo + (size_t)l * 1048576, Wo, Wo, 1024, 1024, 1024, BIG, BIG, h, 1024, 0, 32);
        rms_kernel<<<32, 256>>>(h, ln2 + l * 1024, x, gu, 49152);
        gemm32<4><<<dim3(12, 16), 256>>>(x, 1024, 0,
            Wg + (size_t)l * 3145728, Wu + (size_t)l * 3145728, Wu,
            3072, 3072, 3072, 3072, BIG, gu, 6144, 0, 64);
        gemm32<4><<<dim3(2, 96), 256>>>(gu, 6144, 3072,
            Wd + (size_t)l * 3145728, Wd, Wd, 1024, 1024, 1024, BIG, BIG, h, 1024, 0, 32);
    }

    rms_kernel<<<32, 256>>>(h, normw, x, oh, 8192);
    gemm32<2><<<dim3(4, 32), 256>>>(x, 1024, 0, Wout, Wout, Wout,
        1024, 1024, 1024, BIG, BIG, oh, 1024, 1, 32);
}